// round 7
// baseline (speedup 1.0000x reference)
#include <cuda_runtime.h>
#include <cuda_bf16.h>
#include <cstdint>

// Problem constants
#define D_MODEL   512
#define NUM_RULES 16
#define BATCH     4
#define SEQ       4096
#define M_TOTAL   (BATCH * SEQ)          // 16384

// GEMM tiling
#define BM 128
#define BN 128
#define BK 16
#define NTHREADS 256
#define KTILES          (D_MODEL / BK)   // 32
#define ROWBLOCKS       (M_TOTAL / BM)   // 128
#define ROWBLK_PER_B    (SEQ / BM)       // 32

// Scratch (static __device__ globals: allocation-free per harness rules)
__device__ float g_H[(size_t)M_TOTAL * D_MODEL];                 // 32 MB: silu(X@Wa1+b)
__device__ float g_part[NUM_RULES * ROWBLOCKS * D_MODEL];        // 16 MB: per-rowblock sigmoid col-sums
__device__ float g_cond[BATCH * NUM_RULES * D_MODEL];            // 128 KB: mean_s sigmoid(...)

__device__ __forceinline__ float sigmoidf_(float v) {
    return 1.0f / (1.0f + __expf(-v));
}

// MODE 0: C = sigmoid(X@Wc[r]+bc[r]); column-sum over the 128 rows of this block
//         -> g_part[r][blockIdx.y][col]   (rule = blockIdx.z)
// MODE 1: g_H = silu(X@Wa1[r]+ba1[r])
// MODE 2: OUT (+)= (g_H@Wa2[r]+ba2[r]) * g_cond[b][r][col]
template <int MODE>
__global__ __launch_bounds__(NTHREADS, 2)
void rb_gemm(const float* __restrict__ X,
             const float* __restrict__ Wbase,
             const float* __restrict__ Bbase,
             float* __restrict__ OUT,
             int rule, int accumulate)
{
    const int r = (MODE == 0) ? (int)blockIdx.z : rule;
    const float* __restrict__ A    = (MODE == 2) ? g_H : X;
    const float* __restrict__ W    = Wbase + (size_t)r * D_MODEL * D_MODEL;
    const float* __restrict__ bias = Bbase + r * D_MODEL;

    const int tid = threadIdx.x;
    const int tx  = tid & 15;   // col group (8 cols each)
    const int ty  = tid >> 4;   // row group (8 rows each)
    const int rowBase = blockIdx.y * BM;
    const int colBase = blockIdx.x * BN;

    __shared__ float As[2][BK][BM + 4];   // +4 pad: kills transpose-store conflicts
    __shared__ float Bs[2][BK][BN];
    __shared__ float red[(MODE == 0) ? 16 : 1][BN];

    // Global-load mapping: 2 float4 per thread per tile for each of A and B
    const int aRow = tid >> 1;            // 0..127
    const int aQ   = (tid & 1);           // K-quad = aQ + 2*j
    const int bRow = tid >> 4;            // 0..15
    const int bQ   = tid & 15;            // N-quad = bQ + 16*j (contiguous 256B per half-warp)

    const float* aPtr = A + (size_t)(rowBase + aRow) * D_MODEL;
    const float* wPtr = W + colBase;

    float4 aReg[2], bReg[2];

    // Prologue: tile 0 -> smem buf 0
    {
        #pragma unroll
        for (int j = 0; j < 2; ++j) {
            aReg[j] = *(const float4*)(aPtr + (aQ + 2 * j) * 4);
            bReg[j] = *(const float4*)(wPtr + (size_t)bRow * D_MODEL + (bQ + 16 * j) * 4);
        }
        #pragma unroll
        for (int j = 0; j < 2; ++j) {
            const int q = aQ + 2 * j;
            As[0][q * 4 + 0][aRow] = aReg[j].x;
            As[0][q * 4 + 1][aRow] = aReg[j].y;
            As[0][q * 4 + 2][aRow] = aReg[j].z;
            As[0][q * 4 + 3][aRow] = aReg[j].w;
            *(float4*)&Bs[0][bRow][(bQ + 16 * j) * 4] = bReg[j];
        }
    }
    __syncthreads();

    float acc[8][8];
    #pragma unroll
    for (int i = 0; i < 8; ++i)
        #pragma unroll
        for (int j2 = 0; j2 < 8; ++j2) acc[i][j2] = 0.0f;

    int buf = 0;
    for (int kt = 0; kt < KTILES; ++kt) {
        if (kt + 1 < KTILES) {
            const int k0 = (kt + 1) * BK;
            #pragma unroll
            for (int j = 0; j < 2; ++j) {
                aReg[j] = *(const float4*)(aPtr + k0 + (aQ + 2 * j) * 4);
                bReg[j] = *(const float4*)(wPtr + (size_t)(k0 + bRow) * D_MODEL + (bQ + 16 * j) * 4);
            }
        }
        #pragma unroll
        for (int k = 0; k < BK; ++k) {
            float a[8], b[8];
            float4 t0 = *(const float4*)&As[buf][k][ty * 8];
            float4 t1 = *(const float4*)&As[buf][k][ty * 8 + 4];
            float4 t2 = *(const float4*)&Bs[buf][k][tx * 8];
            float4 t3 = *(const float4*)&Bs[buf][k][tx * 8 + 4];
            a[0]=t0.x; a[1]=t0.y; a[2]=t0.z; a[3]=t0.w;
            a[4]=t1.x; a[5]=t1.y; a[6]=t1.z; a[7]=t1.w;
            b[0]=t2.x; b[1]=t2.y; b[2]=t2.z; b[3]=t2.w;
            b[4]=t3.x; b[5]=t3.y; b[6]=t3.z; b[7]=t3.w;
            #pragma unroll
            for (int i = 0; i < 8; ++i)
                #pragma unroll
                for (int j2 = 0; j2 < 8; ++j2)
                    acc[i][j2] += a[i] * b[j2];
        }
        if (kt + 1 < KTILES) {
            const int nb = buf ^ 1;
            #pragma unroll
            for (int j = 0; j < 2; ++j) {
                const int q = aQ + 2 * j;
                As[nb][q * 4 + 0][aRow] = aReg[j].x;
                As[nb][q * 4 + 1][aRow] = aReg[j].y;
                As[nb][q * 4 + 2][aRow] = aReg[j].z;
                As[nb][q * 4 + 3][aRow] = aReg[j].w;
                *(float4*)&Bs[nb][bRow][(bQ + 16 * j) * 4] = bReg[j];
            }
            __syncthreads();
            buf = nb;
        }
    }

    // Bias for this thread's 8 columns
    float bv[8];
    {
        float4 u0 = *(const float4*)(bias + colBase + tx * 8);
        float4 u1 = *(const float4*)(bias + colBase + tx * 8 + 4);
        bv[0]=u0.x; bv[1]=u0.y; bv[2]=u0.z; bv[3]=u0.w;
        bv[4]=u1.x; bv[5]=u1.y; bv[6]=u1.z; bv[7]=u1.w;
    }

    if (MODE == 0) {
        float s[8];
        #pragma unroll
        for (int j2 = 0; j2 < 8; ++j2) s[j2] = 0.0f;
        #pragma unroll
        for (int i = 0; i < 8; ++i)
            #pragma unroll
            for (int j2 = 0; j2 < 8; ++j2)
                s[j2] += sigmoidf_(acc[i][j2] + bv[j2]);
        #pragma unroll
        for (int j2 = 0; j2 < 8; ++j2) red[ty][tx * 8 + j2] = s[j2];
        __syncthreads();
        if (ty == 0) {
            float* dst = &g_part[((size_t)r * ROWBLOCKS + blockIdx.y) * D_MODEL + colBase + tx * 8];
            #pragma unroll
            for (int j2 = 0; j2 < 8; ++j2) {
                float t = 0.0f;
                #pragma unroll
                for (int q = 0; q < 16; ++q) t += red[q][tx * 8 + j2];
                dst[j2] = t;   // deterministic: no atomics
            }
        }
    } else if (MODE == 1) {
        #pragma unroll
        for (int i = 0; i < 8; ++i) {
            const int row = rowBase + ty * 8 + i;
            float v[8];
            #pragma unroll
            for (int j2 = 0; j2 < 8; ++j2) {
                const float z = acc[i][j2] + bv[j2];
                v[j2] = z * sigmoidf_(z);            // silu
            }
            float4* o = (float4*)&g_H[(size_t)row * D_MODEL + colBase + tx * 8];
            o[0] = make_float4(v[0], v[1], v[2], v[3]);
            o[1] = make_float4(v[4], v[5], v[6], v[7]);
        }
    } else {
        const int b = rowBase / SEQ;   // BM=128 divides SEQ=4096 -> block is single-batch
        float cv[8];
        {
            const float* cp = &g_cond[((b * NUM_RULES) + r) * D_MODEL + colBase + tx * 8];
            float4 c0 = *(const float4*)cp;
            float4 c1 = *(const float4*)(cp + 4);
            cv[0]=c0.x; cv[1]=c0.y; cv[2]=c0.z; cv[3]=c0.w;
            cv[4]=c1.x; cv[5]=c1.y; cv[6]=c1.z; cv[7]=c1.w;
        }
        #pragma unroll
        for (int i = 0; i < 8; ++i) {
            const int row = rowBase + ty * 8 + i;
            float4* o = (float4*)&OUT[(size_t)row * D_MODEL + colBase + tx * 8];
            float v[8];
            #pragma unroll
            for (int j2 = 0; j2 < 8; ++j2)
                v[j2] = (acc[i][j2] + bv[j2]) * cv[j2];
            if (accumulate) {
                float4 p0 = o[0], p1 = o[1];
                v[0]+=p0.x; v[1]+=p0.y; v[2]+=p0.z; v[3]+=p0.w;
                v[4]+=p1.x; v[5]+=p1.y; v[6]+=p1.z; v[7]+=p1.w;
            }
            o[0] = make_float4(v[0], v[1], v[2], v[3]);
            o[1] = make_float4(v[4], v[5], v[6], v[7]);
        }
    }
}

// g_cond[b][r][d] = (1/SEQ) * sum over the 32 row-blocks of batch b of g_part[r][..][d]
__global__ void reduce_cond_kernel() {
    const int i = blockIdx.x * blockDim.x + threadIdx.x;
    if (i >= BATCH * NUM_RULES * D_MODEL) return;
    const int d = i % D_MODEL;
    const int t = i / D_MODEL;
    const int r = t % NUM_RULES;
    const int b = t / NUM_RULES;
    float s = 0.0f;
    #pragma unroll 4
    for (int q = 0; q < ROWBLK_PER_B; ++q)
        s += g_part[((size_t)r * ROWBLOCKS + b * ROWBLK_PER_B + q) * D_MODEL + d];
    g_cond[i] = s * (1.0f / (float)SEQ);
}

extern "C" void kernel_launch(void* const* d_in, const int* in_sizes, int n_in,
                              void* d_out, int out_size) {
    const float* X   = (const float*)d_in[0];   // [4,4096,512]
    const float* Wc  = (const float*)d_in[1];   // [16,512,512]
    const float* bc  = (const float*)d_in[2];   // [16,512]
    const float* Wa1 = (const float*)d_in[3];
    const float* ba1 = (const float*)d_in[4];
    const float* Wa2 = (const float*)d_in[5];
    const float* ba2 = (const float*)d_in[6];
    float* out = (float*)d_out;
    (void)in_sizes; (void)n_in; (void)out_size;

    const dim3 blk(NTHREADS);

    // Phase 1: condition scores for all 16 rules in one batched launch
    const dim3 gridC(D_MODEL / BN, M_TOTAL / BM, NUM_RULES);
    rb_gemm<0><<<gridC, blk>>>(X, Wc, bc, nullptr, 0, 0);
    reduce_cond_kernel<<<(BATCH * NUM_RULES * D_MODEL + 255) / 256, 256>>>();

    // Phase 2: per rule: H = silu(X@Wa1+b); out (+)= (H@Wa2+b) * cond
    const dim3 grid(D_MODEL / BN, M_TOTAL / BM, 1);
    for (int rr = 0; rr < NUM_RULES; ++rr) {
        rb_gemm<1><<<grid, blk>>>(X, Wa1, ba1, nullptr, rr, 0);
        rb_gemm<2><<<grid, blk>>>(X, Wa2, ba2, out, rr, rr > 0);
    }
}

// round 8
// speedup vs baseline: 1.0001x; 1.0001x over previous
#include <cuda_runtime.h>
#include <cuda_bf16.h>
#include <cstdint>

// Problem constants
#define D_MODEL   512
#define NUM_RULES 16
#define BATCH     4
#define SEQ       4096
#define M_TOTAL   (BATCH * SEQ)          // 16384

// GEMM tiling
#define BM 128
#define BN 128
#define BK 16
#define NTHREADS 256
#define KTILES          (D_MODEL / BK)   // 32
#define ROWBLOCKS       (M_TOTAL / BM)   // 128
#define ROWBLK_PER_B    (SEQ / BM)       // 32

// Scratch (static __device__ globals: allocation-free per harness rules)
__device__ float g_H[(size_t)M_TOTAL * D_MODEL];                 // 32 MB: silu(X@Wa1+b)
__device__ float g_part[NUM_RULES * ROWBLOCKS * D_MODEL];        // 16 MB: per-rowblock sigmoid col-sums
__device__ float g_cond[BATCH * NUM_RULES * D_MODEL];            // 128 KB: mean_s sigmoid(...)

__device__ __forceinline__ float sigmoidf_(float v) {
    return 1.0f / (1.0f + __expf(-v));
}

// MODE 0: C = sigmoid(X@Wc[r]+bc[r]); column-sum over the 128 rows of this block
//         -> g_part[r][blockIdx.y][col]   (rule = blockIdx.z)
// MODE 1: g_H = silu(X@Wa1[r]+ba1[r])
// MODE 2: OUT (+)= (g_H@Wa2[r]+ba2[r]) * g_cond[b][r][col]
template <int MODE>
__global__ __launch_bounds__(NTHREADS, 2)
void rb_gemm(const float* __restrict__ X,
             const float* __restrict__ Wbase,
             const float* __restrict__ Bbase,
             float* __restrict__ OUT,
             int rule, int accumulate)
{
    const int r = (MODE == 0) ? (int)blockIdx.z : rule;
    const float* __restrict__ A    = (MODE == 2) ? g_H : X;
    const float* __restrict__ W    = Wbase + (size_t)r * D_MODEL * D_MODEL;
    const float* __restrict__ bias = Bbase + r * D_MODEL;

    const int tid = threadIdx.x;
    const int tx  = tid & 15;   // col group (8 cols each)
    const int ty  = tid >> 4;   // row group (8 rows each)
    const int rowBase = blockIdx.y * BM;
    const int colBase = blockIdx.x * BN;

    __shared__ float As[2][BK][BM + 4];   // +4 pad: kills transpose-store conflicts
    __shared__ float Bs[2][BK][BN];
    __shared__ float red[(MODE == 0) ? 16 : 1][BN];

    // Global-load mapping: 2 float4 per thread per tile for each of A and B
    const int aRow = tid >> 1;            // 0..127
    const int aQ   = (tid & 1);           // K-quad = aQ + 2*j
    const int bRow = tid >> 4;            // 0..15
    const int bQ   = tid & 15;            // N-quad = bQ + 16*j (contiguous 256B per half-warp)

    const float* aPtr = A + (size_t)(rowBase + aRow) * D_MODEL;
    const float* wPtr = W + colBase;

    float4 aReg[2], bReg[2];

    // Prologue: tile 0 -> smem buf 0
    {
        #pragma unroll
        for (int j = 0; j < 2; ++j) {
            aReg[j] = *(const float4*)(aPtr + (aQ + 2 * j) * 4);
            bReg[j] = *(const float4*)(wPtr + (size_t)bRow * D_MODEL + (bQ + 16 * j) * 4);
        }
        #pragma unroll
        for (int j = 0; j < 2; ++j) {
            const int q = aQ + 2 * j;
            As[0][q * 4 + 0][aRow] = aReg[j].x;
            As[0][q * 4 + 1][aRow] = aReg[j].y;
            As[0][q * 4 + 2][aRow] = aReg[j].z;
            As[0][q * 4 + 3][aRow] = aReg[j].w;
            *(float4*)&Bs[0][bRow][(bQ + 16 * j) * 4] = bReg[j];
        }
    }
    __syncthreads();

    float acc[8][8];
    #pragma unroll
    for (int i = 0; i < 8; ++i)
        #pragma unroll
        for (int j2 = 0; j2 < 8; ++j2) acc[i][j2] = 0.0f;

    int buf = 0;
    for (int kt = 0; kt < KTILES; ++kt) {
        if (kt + 1 < KTILES) {
            const int k0 = (kt + 1) * BK;
            #pragma unroll
            for (int j = 0; j < 2; ++j) {
                aReg[j] = *(const float4*)(aPtr + k0 + (aQ + 2 * j) * 4);
                bReg[j] = *(const float4*)(wPtr + (size_t)(k0 + bRow) * D_MODEL + (bQ + 16 * j) * 4);
            }
        }
        #pragma unroll
        for (int k = 0; k < BK; ++k) {
            float a[8], b[8];
            float4 t0 = *(const float4*)&As[buf][k][ty * 8];
            float4 t1 = *(const float4*)&As[buf][k][ty * 8 + 4];
            float4 t2 = *(const float4*)&Bs[buf][k][tx * 8];
            float4 t3 = *(const float4*)&Bs[buf][k][tx * 8 + 4];
            a[0]=t0.x; a[1]=t0.y; a[2]=t0.z; a[3]=t0.w;
            a[4]=t1.x; a[5]=t1.y; a[6]=t1.z; a[7]=t1.w;
            b[0]=t2.x; b[1]=t2.y; b[2]=t2.z; b[3]=t2.w;
            b[4]=t3.x; b[5]=t3.y; b[6]=t3.z; b[7]=t3.w;
            #pragma unroll
            for (int i = 0; i < 8; ++i)
                #pragma unroll
                for (int j2 = 0; j2 < 8; ++j2)
                    acc[i][j2] += a[i] * b[j2];
        }
        if (kt + 1 < KTILES) {
            const int nb = buf ^ 1;
            #pragma unroll
            for (int j = 0; j < 2; ++j) {
                const int q = aQ + 2 * j;
                As[nb][q * 4 + 0][aRow] = aReg[j].x;
                As[nb][q * 4 + 1][aRow] = aReg[j].y;
                As[nb][q * 4 + 2][aRow] = aReg[j].z;
                As[nb][q * 4 + 3][aRow] = aReg[j].w;
                *(float4*)&Bs[nb][bRow][(bQ + 16 * j) * 4] = bReg[j];
            }
            __syncthreads();
            buf = nb;
        }
    }

    // Bias for this thread's 8 columns
    float bv[8];
    {
        float4 u0 = *(const float4*)(bias + colBase + tx * 8);
        float4 u1 = *(const float4*)(bias + colBase + tx * 8 + 4);
        bv[0]=u0.x; bv[1]=u0.y; bv[2]=u0.z; bv[3]=u0.w;
        bv[4]=u1.x; bv[5]=u1.y; bv[6]=u1.z; bv[7]=u1.w;
    }

    if (MODE == 0) {
        float s[8];
        #pragma unroll
        for (int j2 = 0; j2 < 8; ++j2) s[j2] = 0.0f;
        #pragma unroll
        for (int i = 0; i < 8; ++i)
            #pragma unroll
            for (int j2 = 0; j2 < 8; ++j2)
                s[j2] += sigmoidf_(acc[i][j2] + bv[j2]);
        #pragma unroll
        for (int j2 = 0; j2 < 8; ++j2) red[ty][tx * 8 + j2] = s[j2];
        __syncthreads();
        if (ty == 0) {
            float* dst = &g_part[((size_t)r * ROWBLOCKS + blockIdx.y) * D_MODEL + colBase + tx * 8];
            #pragma unroll
            for (int j2 = 0; j2 < 8; ++j2) {
                float t = 0.0f;
                #pragma unroll
                for (int q = 0; q < 16; ++q) t += red[q][tx * 8 + j2];
                dst[j2] = t;   // deterministic: no atomics
            }
        }
    } else if (MODE == 1) {
        #pragma unroll
        for (int i = 0; i < 8; ++i) {
            const int row = rowBase + ty * 8 + i;
            float v[8];
            #pragma unroll
            for (int j2 = 0; j2 < 8; ++j2) {
                const float z = acc[i][j2] + bv[j2];
                v[j2] = z * sigmoidf_(z);            // silu
            }
            float4* o = (float4*)&g_H[(size_t)row * D_MODEL + colBase + tx * 8];
            o[0] = make_float4(v[0], v[1], v[2], v[3]);
            o[1] = make_float4(v[4], v[5], v[6], v[7]);
        }
    } else {
        const int b = rowBase / SEQ;   // BM=128 divides SEQ=4096 -> block is single-batch
        float cv[8];
        {
            const float* cp = &g_cond[((b * NUM_RULES) + r) * D_MODEL + colBase + tx * 8];
            float4 c0 = *(const float4*)cp;
            float4 c1 = *(const float4*)(cp + 4);
            cv[0]=c0.x; cv[1]=c0.y; cv[2]=c0.z; cv[3]=c0.w;
            cv[4]=c1.x; cv[5]=c1.y; cv[6]=c1.z; cv[7]=c1.w;
        }
        #pragma unroll
        for (int i = 0; i < 8; ++i) {
            const int row = rowBase + ty * 8 + i;
            float4* o = (float4*)&OUT[(size_t)row * D_MODEL + colBase + tx * 8];
            float v[8];
            #pragma unroll
            for (int j2 = 0; j2 < 8; ++j2)
                v[j2] = (acc[i][j2] + bv[j2]) * cv[j2];
            if (accumulate) {
                float4 p0 = o[0], p1 = o[1];
                v[0]+=p0.x; v[1]+=p0.y; v[2]+=p0.z; v[3]+=p0.w;
                v[4]+=p1.x; v[5]+=p1.y; v[6]+=p1.z; v[7]+=p1.w;
            }
            o[0] = make_float4(v[0], v[1], v[2], v[3]);
            o[1] = make_float4(v[4], v[5], v[6], v[7]);
        }
    }
}

// g_cond[b][r][d] = (1/SEQ) * sum over the 32 row-blocks of batch b of g_part[r][..][d]
__global__ void reduce_cond_kernel() {
    const int i = blockIdx.x * blockDim.x + threadIdx.x;
    if (i >= BATCH * NUM_RULES * D_MODEL) return;
    const int d = i % D_MODEL;
    const int t = i / D_MODEL;
    const int r = t % NUM_RULES;
    const int b = t / NUM_RULES;
    float s = 0.0f;
    #pragma unroll 4
    for (int q = 0; q < ROWBLK_PER_B; ++q)
        s += g_part[((size_t)r * ROWBLOCKS + b * ROWBLK_PER_B + q) * D_MODEL + d];
    g_cond[i] = s * (1.0f / (float)SEQ);
}

extern "C" void kernel_launch(void* const* d_in, const int* in_sizes, int n_in,
                              void* d_out, int out_size) {
    const float* X   = (const float*)d_in[0];   // [4,4096,512]
    const float* Wc  = (const float*)d_in[1];   // [16,512,512]
    const float* bc  = (const float*)d_in[2];   // [16,512]
    const float* Wa1 = (const float*)d_in[3];
    const float* ba1 = (const float*)d_in[4];
    const float* Wa2 = (const float*)d_in[5];
    const float* ba2 = (const float*)d_in[6];
    float* out = (float*)d_out;
    (void)in_sizes; (void)n_in; (void)out_size;

    const dim3 blk(NTHREADS);

    // Phase 1: condition scores for all 16 rules in one batched launch
    const dim3 gridC(D_MODEL / BN, M_TOTAL / BM, NUM_RULES);
    rb_gemm<0><<<gridC, blk>>>(X, Wc, bc, nullptr, 0, 0);
    reduce_cond_kernel<<<(BATCH * NUM_RULES * D_MODEL + 255) / 256, 256>>>();

    // Phase 2: per rule: H = silu(X@Wa1+b); out (+)= (H@Wa2+b) * cond
    const dim3 grid(D_MODEL / BN, M_TOTAL / BM, 1);
    for (int rr = 0; rr < NUM_RULES; ++rr) {
        rb_gemm<1><<<grid, blk>>>(X, Wa1, ba1, nullptr, rr, 0);
        rb_gemm<2><<<grid, blk>>>(X, Wa2, ba2, out, rr, rr > 0);
    }
}

// round 15
// speedup vs baseline: 1.0262x; 1.0261x over previous
#include <cuda_runtime.h>
#include <cuda_bf16.h>
#include <cstdint>

// Problem constants
#define D_MODEL   512
#define NUM_RULES 16
#define BATCH     4
#define SEQ       4096
#define M_TOTAL   (BATCH * SEQ)          // 16384

// GEMM tiling (identical to the proven R7 kernel)
#define BM 128
#define BN 128
#define BK 16
#define NTHREADS 256
#define KTILES          (D_MODEL / BK)   // 32
#define ROWBLOCKS       (M_TOTAL / BM)   // 128
#define ROWBLK_PER_B    (SEQ / BM)       // 32

// Scratch (static __device__ globals: allocation-free per harness rules)
__device__ float g_H[(size_t)M_TOTAL * D_MODEL];                 // 32 MB: silu(X@Wa1+b)
__device__ float g_part[NUM_RULES * ROWBLOCKS * D_MODEL];        // 16 MB: per-rowblock sigmoid col-sums
__device__ float g_cond[BATCH * NUM_RULES * D_MODEL];            // 128 KB: mean_seq sigmoid(...)

__device__ __forceinline__ float sigmoidf_(float v) {
    return 1.0f / (1.0f + __expf(-v));
}

// ---- Blackwell packed fp32 pair helpers (FFMA2 via PTX f32x2) ----
__device__ __forceinline__ uint64_t packf2(float lo, float hi) {
    uint64_t p;
    asm("mov.b64 %0, {%1, %2};" : "=l"(p)
        : "r"(__float_as_uint(lo)), "r"(__float_as_uint(hi)));
    return p;
}
__device__ __forceinline__ void unpackf2(uint64_t p, float& lo, float& hi) {
    uint32_t a, b;
    asm("mov.b64 {%0, %1}, %2;" : "=r"(a), "=r"(b) : "l"(p));
    lo = __uint_as_float(a);
    hi = __uint_as_float(b);
}
__device__ __forceinline__ void ffma2(uint64_t& d, uint64_t a, uint64_t b) {
    asm("fma.rn.f32x2 %0, %1, %2, %0;" : "+l"(d) : "l"(a), "l"(b));
}

// MODE 0: C = sigmoid(X@Wc[r]+bc[r]); column-sum over the 128 rows of this block
//         -> g_part[r][blockIdx.y][col]   (rule = blockIdx.z)
// MODE 1: g_H = silu(X@Wa1[r]+ba1[r])
// MODE 2: OUT (+)= (g_H@Wa2[r]+ba2[r]) * g_cond[b][r][col]
template <int MODE>
__global__ __launch_bounds__(NTHREADS, 2)
void rb_gemm(const float* __restrict__ X,
             const float* __restrict__ Wbase,
             const float* __restrict__ Bbase,
             float* __restrict__ OUT,
             int rule, int accumulate)
{
    const int r = (MODE == 0) ? (int)blockIdx.z : rule;
    const float* __restrict__ A    = (MODE == 2) ? g_H : X;
    const float* __restrict__ W    = Wbase + (size_t)r * D_MODEL * D_MODEL;
    const float* __restrict__ bias = Bbase + r * D_MODEL;

    const int tid = threadIdx.x;
    const int tx  = tid & 15;   // col group (8 cols each)
    const int ty  = tid >> 4;   // row group (8 rows each)
    const int rowBase = blockIdx.y * BM;
    const int colBase = blockIdx.x * BN;

    __shared__ float As[2][BK][BM + 4];   // +4 pad: kills transpose-store conflicts
    __shared__ float Bs[2][BK][BN];
    __shared__ float red[(MODE == 0) ? 16 : 1][BN];

    // Global-load mapping: 2 float4 per thread per tile for each of A and B
    const int aRow = tid >> 1;            // 0..127
    const int aQ   = (tid & 1);           // K-quad = aQ + 2*j
    const int bRow = tid >> 4;            // 0..15
    const int bQ   = tid & 15;            // N-quad = bQ + 16*j

    const float* aPtr = A + (size_t)(rowBase + aRow) * D_MODEL;
    const float* wPtr = W + colBase;

    float4 aReg[2], bReg[2];

    // Prologue: tile 0 -> smem buf 0
    {
        #pragma unroll
        for (int j = 0; j < 2; ++j) {
            aReg[j] = *(const float4*)(aPtr + (aQ + 2 * j) * 4);
            bReg[j] = *(const float4*)(wPtr + (size_t)bRow * D_MODEL + (bQ + 16 * j) * 4);
        }
        #pragma unroll
        for (int j = 0; j < 2; ++j) {
            const int q = aQ + 2 * j;
            As[0][q * 4 + 0][aRow] = aReg[j].x;
            As[0][q * 4 + 1][aRow] = aReg[j].y;
            As[0][q * 4 + 2][aRow] = aReg[j].z;
            As[0][q * 4 + 3][aRow] = aReg[j].w;
            *(float4*)&Bs[0][bRow][(bQ + 16 * j) * 4] = bReg[j];
        }
    }
    __syncthreads();

    // Accumulators as packed f32x2 pairs: acc2[i][jp] holds cols (2jp, 2jp+1) of row i
    uint64_t acc2[8][4];
    #pragma unroll
    for (int i = 0; i < 8; ++i)
        #pragma unroll
        for (int jp = 0; jp < 4; ++jp) acc2[i][jp] = 0ull;   // (0.0f, 0.0f)

    int buf = 0;
    for (int kt = 0; kt < KTILES; ++kt) {
        if (kt + 1 < KTILES) {
            const int k0 = (kt + 1) * BK;
            #pragma unroll
            for (int j = 0; j < 2; ++j) {
                aReg[j] = *(const float4*)(aPtr + k0 + (aQ + 2 * j) * 4);
                bReg[j] = *(const float4*)(wPtr + (size_t)(k0 + bRow) * D_MODEL + (bQ + 16 * j) * 4);
            }
        }
        #pragma unroll
        for (int k = 0; k < BK; ++k) {
            float4 t0 = *(const float4*)&As[buf][k][ty * 8];
            float4 t1 = *(const float4*)&As[buf][k][ty * 8 + 4];
            float4 t2 = *(const float4*)&Bs[buf][k][tx * 8];
            float4 t3 = *(const float4*)&Bs[buf][k][tx * 8 + 4];
            // a broadcast pairs (a_i, a_i); b direct pairs (b_2j, b_2j+1)
            uint64_t ap[8], bp[4];
            ap[0] = packf2(t0.x, t0.x); ap[1] = packf2(t0.y, t0.y);
            ap[2] = packf2(t0.z, t0.z); ap[3] = packf2(t0.w, t0.w);
            ap[4] = packf2(t1.x, t1.x); ap[5] = packf2(t1.y, t1.y);
            ap[6] = packf2(t1.z, t1.z); ap[7] = packf2(t1.w, t1.w);
            bp[0] = packf2(t2.x, t2.y); bp[1] = packf2(t2.z, t2.w);
            bp[2] = packf2(t3.x, t3.y); bp[3] = packf2(t3.z, t3.w);
            #pragma unroll
            for (int i = 0; i < 8; ++i)
                #pragma unroll
                for (int jp = 0; jp < 4; ++jp)
                    ffma2(acc2[i][jp], ap[i], bp[jp]);
        }
        if (kt + 1 < KTILES) {
            const int nb = buf ^ 1;
            #pragma unroll
            for (int j = 0; j < 2; ++j) {
                const int q = aQ + 2 * j;
                As[nb][q * 4 + 0][aRow] = aReg[j].x;
                As[nb][q * 4 + 1][aRow] = aReg[j].y;
                As[nb][q * 4 + 2][aRow] = aReg[j].z;
                As[nb][q * 4 + 3][aRow] = aReg[j].w;
                *(float4*)&Bs[nb][bRow][(bQ + 16 * j) * 4] = bReg[j];
            }
            __syncthreads();
            buf = nb;
        }
    }

    // Unpack accumulators
    float acc[8][8];
    #pragma unroll
    for (int i = 0; i < 8; ++i)
        #pragma unroll
        for (int jp = 0; jp < 4; ++jp)
            unpackf2(acc2[i][jp], acc[i][jp * 2], acc[i][jp * 2 + 1]);

    // Bias for this thread's 8 columns
    float bv[8];
    {
        float4 u0 = *(const float4*)(bias + colBase + tx * 8);
        float4 u1 = *(const float4*)(bias + colBase + tx * 8 + 4);
        bv[0]=u0.x; bv[1]=u0.y; bv[2]=u0.z; bv[3]=u0.w;
        bv[4]=u1.x; bv[5]=u1.y; bv[6]=u1.z; bv[7]=u1.w;
    }

    if (MODE == 0) {
        float s[8];
        #pragma unroll
        for (int j2 = 0; j2 < 8; ++j2) s[j2] = 0.0f;
        #pragma unroll
        for (int i = 0; i < 8; ++i)
            #pragma unroll
            for (int j2 = 0; j2 < 8; ++j2)
                s[j2] += sigmoidf_(acc[i][j2] + bv[j2]);
        #pragma unroll
        for (int j2 = 0; j2 < 8; ++j2) red[ty][tx * 8 + j2] = s[j2];
        __syncthreads();
        if (ty == 0) {
            float* dst = &g_part[((size_t)r * ROWBLOCKS + blockIdx.y) * D_MODEL + colBase + tx * 8];
            #pragma unroll
            for (int j2 = 0; j2 < 8; ++j2) {
                float t = 0.0f;
                #pragma unroll
                for (int q = 0; q < 16; ++q) t += red[q][tx * 8 + j2];
                dst[j2] = t;   // deterministic: no atomics
            }
        }
    } else if (MODE == 1) {
        #pragma unroll
        for (int i = 0; i < 8; ++i) {
            const int row = rowBase + ty * 8 + i;
            float v[8];
            #pragma unroll
            for (int j2 = 0; j2 < 8; ++j2) {
                const float z = acc[i][j2] + bv[j2];
                v[j2] = z * sigmoidf_(z);            // silu
            }
            float4* o = (float4*)&g_H[(size_t)row * D_MODEL + colBase + tx * 8];
            o[0] = make_float4(v[0], v[1], v[2], v[3]);
            o[1] = make_float4(v[4], v[5], v[6], v[7]);
        }
    } else {
        const int b = rowBase / SEQ;   // BM=128 divides SEQ=4096 -> block is single-batch
        float cv[8];
        {
            const float* cp = &g_cond[((b * NUM_RULES) + r) * D_MODEL + colBase + tx * 8];
            float4 c0 = *(const float4*)cp;
            float4 c1 = *(const float4*)(cp + 4);
            cv[0]=c0.x; cv[1]=c0.y; cv[2]=c0.z; cv[3]=c0.w;
            cv[4]=c1.x; cv[5]=c1.y; cv[6]=c1.z; cv[7]=c1.w;
        }
        #pragma unroll
        for (int i = 0; i < 8; ++i) {
            const int row = rowBase + ty * 8 + i;
            float4* o = (float4*)&OUT[(size_t)row * D_MODEL + colBase + tx * 8];
            float v[8];
            #pragma unroll
            for (int j2 = 0; j2 < 8; ++j2)
                v[j2] = (acc[i][j2] + bv[j2]) * cv[j2];
            if (accumulate) {
                float4 p0 = o[0], p1 = o[1];
                v[0]+=p0.x; v[1]+=p0.y; v[2]+=p0.z; v[3]+=p0.w;
                v[4]+=p1.x; v[5]+=p1.y; v[6]+=p1.z; v[7]+=p1.w;
            }
            o[0] = make_float4(v[0], v[1], v[2], v[3]);
            o[1] = make_float4(v[4], v[5], v[6], v[7]);
        }
    }
}

// g_cond[b][r][d] = (1/SEQ) * sum over the 32 row-blocks of batch b of g_part[r][..][d]
__global__ void reduce_cond_kernel() {
    const int i = blockIdx.x * blockDim.x + threadIdx.x;
    if (i >= BATCH * NUM_RULES * D_MODEL) return;
    const int d = i % D_MODEL;
    const int t = i / D_MODEL;
    const int r = t % NUM_RULES;
    const int b = t / NUM_RULES;
    float s = 0.0f;
    #pragma unroll 4
    for (int q = 0; q < ROWBLK_PER_B; ++q)
        s += g_part[((size_t)r * ROWBLOCKS + b * ROWBLK_PER_B + q) * D_MODEL + d];
    g_cond[i] = s * (1.0f / (float)SEQ);
}

extern "C" void kernel_launch(void* const* d_in, const int* in_sizes, int n_in,
                              void* d_out, int out_size) {
    const float* X   = (const float*)d_in[0];   // [4,4096,512]
    const float* Wc  = (const float*)d_in[1];   // [16,512,512]
    const float* bc  = (const float*)d_in[2];   // [16,512]
    const float* Wa1 = (const float*)d_in[3];
    const float* ba1 = (const float*)d_in[4];
    const float* Wa2 = (const float*)d_in[5];
    const float* ba2 = (const float*)d_in[6];
    float* out = (float*)d_out;
    (void)in_sizes; (void)n_in; (void)out_size;

    const dim3 blk(NTHREADS);

    // Phase 1: condition scores for all 16 rules in one batched launch
    const dim3 gridC(D_MODEL / BN, M_TOTAL / BM, NUM_RULES);
    rb_gemm<0><<<gridC, blk>>>(X, Wc, bc, nullptr, 0, 0);
    reduce_cond_kernel<<<(BATCH * NUM_RULES * D_MODEL + 255) / 256, 256>>>();

    // Phase 2: per rule: H = silu(X@Wa1+b); out (+)= (H@Wa2+b) * cond
    const dim3 grid(D_MODEL / BN, M_TOTAL / BM, 1);
    for (int rr = 0; rr < NUM_RULES; ++rr) {
        rb_gemm<1><<<grid, blk>>>(X, Wa1, ba1, nullptr, rr, 0);
        rb_gemm<2><<<grid, blk>>>(X, Wa2, ba2, out, rr, rr > 0);
    }
}